// round 7
// baseline (speedup 1.0000x reference)
#include <cuda_runtime.h>
#include <cuda_fp16.h>
#include <cstdint>

// ---------------- problem constants ----------------
#define IN_C   64
#define IMG_H  256
#define IMG_W  256
#define OUT_C  128
#define OUT_H  254
#define OUT_W  254
#define NPOS   (IMG_H * IMG_W)          // 65536
#define NTAPS  9
#define OUT_HW (OUT_H * OUT_W)

// CTA tile: M=128 (all oc), N=256 (full output row), K=64 per tap
#define N_TILE 256

// smem layout
#define SM_A          0                  // 2 stages x 16KB (w tap tile, 128x64 fp16)
#define A_STAGE       16384
#define SM_B          32768              // 3 strips (kh), each 260 rows x 128B
#define STRIP_ROWS    260
#define STRIP_CHUNKS  (STRIP_ROWS * 8)   // 2080 16B chunks
#define STRIP_STRIDE  33792              // 33*1024 (>= 260*128), 1024-aligned
#define SMEM_TOTAL    (32768 + 3 * STRIP_STRIDE)   // 134144

// ---------------- device scratch (no allocs allowed) ----------------
__device__ __align__(1024) __half g_x[NPOS * IN_C + 256];    // NHWC fp16 (+pad)
__device__ __align__(1024) __half g_w[NTAPS * OUT_C * IN_C]; // [tap][oc][ic] fp16

// ---------------- helpers ----------------
__device__ __forceinline__ uint32_t smem_u32(const void* p) {
    uint32_t a;
    asm("{ .reg .u64 t; cvta.to.shared.u64 t, %1; cvt.u32.u64 %0, t; }" : "=r"(a) : "l"(p));
    return a;
}
__device__ __forceinline__ uint32_t sw128(uint32_t o) { return o ^ ((o >> 3) & 0x70); }
__device__ __forceinline__ void cp_async16(uint32_t dst, const void* src) {
    asm volatile("cp.async.cg.shared.global [%0], [%1], 16;" :: "r"(dst), "l"(src) : "memory");
}
__device__ __forceinline__ void cp_commit() {
    asm volatile("cp.async.commit_group;" ::: "memory");
}
template <int N>
__device__ __forceinline__ void cp_wait() {
    asm volatile("cp.async.wait_group %0;" :: "n"(N) : "memory");
}
__device__ __forceinline__ void ldsm4(uint32_t* r, uint32_t addr) {
    asm volatile("ldmatrix.sync.aligned.m8n8.x4.shared.b16 {%0,%1,%2,%3}, [%4];"
                 : "=r"(r[0]), "=r"(r[1]), "=r"(r[2]), "=r"(r[3]) : "r"(addr));
}
__device__ __forceinline__ void mma16816(float* d, const uint32_t* a, uint32_t b0, uint32_t b1) {
    asm volatile("mma.sync.aligned.m16n8k16.row.col.f32.f16.f16.f32 "
                 "{%0,%1,%2,%3}, {%4,%5,%6,%7}, {%8,%9}, {%0,%1,%2,%3};"
                 : "+f"(d[0]), "+f"(d[1]), "+f"(d[2]), "+f"(d[3])
                 : "r"(a[0]), "r"(a[1]), "r"(a[2]), "r"(a[3]), "r"(b0), "r"(b1));
}

// ---------------- prep kernels ----------------
// CHW fp32 -> NHWC fp16 via smem transpose. Block handles 64 pos x 64 ic. Grid 1024.
__global__ __launch_bounds__(256) void prep_x(const float* __restrict__ x) {
    __shared__ float s[IN_C][65];
    const int tid  = threadIdx.x;
    const int pos0 = blockIdx.x * 64;

    // read: 1024 float4 per block, 4 per thread, coalesced
#pragma unroll
    for (int i = 0; i < 4; i++) {
        const int r  = tid + i * 256;
        const int ic = r >> 4;
        const int p4 = (r & 15) * 4;
        float4 f = *reinterpret_cast<const float4*>(x + (size_t)ic * NPOS + pos0 + p4);
        s[ic][p4 + 0] = f.x; s[ic][p4 + 1] = f.y;
        s[ic][p4 + 2] = f.z; s[ic][p4 + 3] = f.w;
    }
    __syncthreads();

    // write: 512 16B-chunks per block, 2 per thread, coalesced
#pragma unroll
    for (int i = 0; i < 2; i++) {
        const int c   = tid + i * 256;
        const int pos = c >> 3;
        const int ic0 = (c & 7) * 8;
        uint32_t pk[4];
#pragma unroll
        for (int j = 0; j < 4; j++) {
            __half h0 = __float2half(s[ic0 + 2*j][pos]);
            __half h1 = __float2half(s[ic0 + 2*j + 1][pos]);
            pk[j] = (uint32_t)__half_as_ushort(h0) | ((uint32_t)__half_as_ushort(h1) << 16);
        }
        *reinterpret_cast<uint4*>(g_x + (size_t)(pos0 + pos) * IN_C + ic0) =
            make_uint4(pk[0], pk[1], pk[2], pk[3]);
    }
}

// w[oc][ic][3][3] fp32 -> g_w[tap][oc][ic] fp16
__global__ __launch_bounds__(256) void prep_w(const float* __restrict__ w) {
    const int idx = blockIdx.x * 256 + threadIdx.x;     // < 9*128*64 = 73728
    const int tap = idx >> 13;
    const int oc  = (idx >> 6) & 127;
    const int ic  = idx & 63;
    g_w[idx] = __float2half(w[((size_t)oc * IN_C + ic) * NTAPS + tap]);
}

// ---------------- main HMMA conv kernel ----------------
// grid (254): one CTA per output row. 512 threads = 16 warps (2 M-groups x 8 N-groups).
__global__ __launch_bounds__(512, 1)
void conv_hmma(const float* __restrict__ bias, float* __restrict__ out)
{
    extern __shared__ char smem[];
    const uint32_t sbase = smem_u32(smem);
    const int tid  = threadIdx.x;
    const int lane = tid & 31;
    const int wid  = tid >> 5;
    const int wm   = wid & 1;            // oc 0-63 / 64-127
    const int wn   = wid >> 1;           // 0..7, 32 positions each
    const int oh   = blockIdx.x;

    // ldmatrix per-lane address components (validated mapping)
    const int rowA = ((lane >> 3) & 1) * 8 + (lane & 7);
    const int kbA  = (lane >> 4) * 16;
    const int rowB = ((lane >> 4) & 1) * 8 + (lane & 7);
    const int kbB  = ((lane >> 3) & 1) * 16;

    float acc[4][4][4];
#pragma unroll
    for (int a = 0; a < 4; a++)
#pragma unroll
        for (int b = 0; b < 4; b++)
#pragma unroll
            for (int c = 0; c < 4; c++) acc[a][b][c] = 0.0f;

    // ---- load the 3 B strips (once per CTA) ----
    auto issue_strips = [&]() {
        for (int i = tid; i < 3 * STRIP_CHUNKS; i += 512) {
            const int strip = i / STRIP_CHUNKS;
            const int c     = i - strip * STRIP_CHUNKS;
            const int y0    = (oh + strip) * IMG_W;
            cp_async16(sbase + SM_B + strip * STRIP_STRIDE + sw128((uint32_t)c * 16),
                       g_x + (size_t)y0 * IN_C + c * 8);
        }
    };
    // ---- load one weight tap tile into a stage ----
    auto issue_A = [&](int tap, int s) {
        const __half* src = g_w + (size_t)tap * OUT_C * IN_C;
        const uint32_t sb = sbase + SM_A + s * A_STAGE;
#pragma unroll
        for (int i = 0; i < 2; i++) {
            const uint32_t chunk = tid + i * 512;          // 0..1023
            cp_async16(sb + sw128(chunk * 16), src + chunk * 8);
        }
    };

    issue_strips();
    issue_A(0, 0);
    cp_commit();            // g0: strips + A0
    issue_A(1, 1);
    cp_commit();            // g1: A1

#pragma unroll 1
    for (int t = 0; t < NTAPS; t++) {
        if (t < NTAPS - 1) cp_wait<1>(); else cp_wait<0>();
        __syncthreads();

        const int kh = t / 3;
        const int kw = t - kh * 3;
        const uint32_t aBase = sbase + SM_A + (t & 1) * A_STAGE;
        const uint32_t bBase = sbase + SM_B + kh * STRIP_STRIDE;

#pragma unroll
        for (int kc = 0; kc < 4; kc++) {
            uint32_t a[4][4];
#pragma unroll
            for (int mi = 0; mi < 4; mi++) {
                const uint32_t o = (uint32_t)(wm * 64 + mi * 16 + rowA) * 128 + kc * 32 + kbA;
                ldsm4(a[mi], aBase + sw128(o));
            }
#pragma unroll
            for (int nj = 0; nj < 2; nj++) {
                uint32_t b[4];
                const uint32_t brow = (uint32_t)(kw + wn * 32 + nj * 16 + rowB);
                const uint32_t o = brow * 128 + kc * 32 + kbB;
                ldsm4(b, bBase + sw128(o));
#pragma unroll
                for (int mi = 0; mi < 4; mi++) {
                    mma16816(acc[mi][nj * 2],     a[mi], b[0], b[1]);
                    mma16816(acc[mi][nj * 2 + 1], a[mi], b[2], b[3]);
                }
            }
        }
        __syncthreads();
        if (t + 2 < NTAPS) { issue_A(t + 2, t & 1); cp_commit(); }
    }

    // ---- epilogue: direct gmem stores ----
#pragma unroll
    for (int mi = 0; mi < 4; mi++) {
        const int oc0 = wm * 64 + mi * 16 + (lane >> 2);
        const float b0 = bias[oc0];
        const float b1 = bias[oc0 + 8];
#pragma unroll
        for (int ni = 0; ni < 4; ni++) {
            const int owp = wn * 32 + ni * 8 + (lane & 3) * 2;
            if (owp < OUT_W) {
                float2 v0 = make_float2(acc[mi][ni][0] + b0, acc[mi][ni][1] + b0);
                float2 v1 = make_float2(acc[mi][ni][2] + b1, acc[mi][ni][3] + b1);
                *reinterpret_cast<float2*>(out + (size_t)oc0 * OUT_HW + oh * OUT_W + owp) = v0;
                *reinterpret_cast<float2*>(out + (size_t)(oc0 + 8) * OUT_HW + oh * OUT_W + owp) = v1;
            }
        }
    }
}

// ---------------- launch ----------------
extern "C" void kernel_launch(void* const* d_in, const int* in_sizes, int n_in,
                              void* d_out, int out_size)
{
    const float* x    = (const float*)d_in[0];
    const float* w    = (const float*)d_in[1];
    const float* bias = (const float*)d_in[2];
    float* out        = (float*)d_out;

    cudaFuncSetAttribute(conv_hmma, cudaFuncAttributeMaxDynamicSharedMemorySize, SMEM_TOTAL);

    prep_x<<<NPOS / 64, 256>>>(x);
    prep_w<<<(NTAPS * OUT_C * IN_C) / 256, 256>>>(w);
    conv_hmma<<<OUT_H, 512, SMEM_TOTAL>>>(bias, out);
}

// round 8
// speedup vs baseline: 1.0984x; 1.0984x over previous
#include <cuda_runtime.h>
#include <cuda_fp16.h>
#include <cstdint>

// ---------------- problem constants ----------------
#define IN_C   64
#define IMG_H  256
#define IMG_W  256
#define OUT_C  128
#define OUT_H  254
#define OUT_W  254
#define NPOS   (IMG_H * IMG_W)          // 65536
#define NTAPS  9
#define OUT_HW (OUT_H * OUT_W)

// CTA tile: M=128 (all oc), N=128 (positions), K=64 per tap (R6 config)
#define N_TILE 128

// smem layout: 3-stage A ring + 3 B strips
#define SM_A          0                  // 3 stages x 16KB (w tap tile, 128x64 fp16)
#define A_STAGE       16384
#define SM_B          49152              // 3 strips (kh) x 136 rows x 128B
#define STRIP_STRIDE  17408              // 136*128, 1024-aligned
#define STRIP_CHUNKS  1040               // 130 rows x 8 chunks
#define SMEM_TOTAL    (49152 + 3 * STRIP_STRIDE)   // 101376

// ---------------- device scratch (no allocs allowed) ----------------
__device__ __align__(1024) __half g_x[NPOS * IN_C + 256];    // NHWC fp16 (+pad)
__device__ __align__(1024) __half g_w[NTAPS * OUT_C * IN_C]; // [tap][oc][ic] fp16

// ---------------- helpers ----------------
__device__ __forceinline__ uint32_t smem_u32(const void* p) {
    uint32_t a;
    asm("{ .reg .u64 t; cvta.to.shared.u64 t, %1; cvt.u32.u64 %0, t; }" : "=r"(a) : "l"(p));
    return a;
}
__device__ __forceinline__ uint32_t sw128(uint32_t o) { return o ^ ((o >> 3) & 0x70); }
__device__ __forceinline__ void cp_async16(uint32_t dst, const void* src) {
    asm volatile("cp.async.cg.shared.global [%0], [%1], 16;" :: "r"(dst), "l"(src) : "memory");
}
__device__ __forceinline__ void cp_commit() {
    asm volatile("cp.async.commit_group;" ::: "memory");
}
template <int N>
__device__ __forceinline__ void cp_wait() {
    asm volatile("cp.async.wait_group %0;" :: "n"(N) : "memory");
}
__device__ __forceinline__ void ldsm4(uint32_t* r, uint32_t addr) {
    asm volatile("ldmatrix.sync.aligned.m8n8.x4.shared.b16 {%0,%1,%2,%3}, [%4];"
                 : "=r"(r[0]), "=r"(r[1]), "=r"(r[2]), "=r"(r[3]) : "r"(addr));
}
__device__ __forceinline__ void mma16816(float* d, const uint32_t* a, uint32_t b0, uint32_t b1) {
    asm volatile("mma.sync.aligned.m16n8k16.row.col.f32.f16.f16.f32 "
                 "{%0,%1,%2,%3}, {%4,%5,%6,%7}, {%8,%9}, {%0,%1,%2,%3};"
                 : "+f"(d[0]), "+f"(d[1]), "+f"(d[2]), "+f"(d[3])
                 : "r"(a[0]), "r"(a[1]), "r"(a[2]), "r"(a[3]), "r"(b0), "r"(b1));
}

// ---------------- fused prep kernel ----------------
// blocks [0,512): CHW fp32 -> NHWC fp16 transpose, 128 pos x 64 ic each.
// blocks [512,800): weight repack w[oc][ic][3][3] -> g_w[tap][oc][ic].
__global__ __launch_bounds__(256) void prep(const float* __restrict__ x,
                                            const float* __restrict__ w) {
    const int tid = threadIdx.x;
    if (blockIdx.x < 512) {
        __shared__ float s[IN_C][129];
        const int pos0 = blockIdx.x * 128;
        // read: 2048 float4 per block, 8 per thread, coalesced
#pragma unroll
        for (int i = 0; i < 8; i++) {
            const int r  = tid + i * 256;
            const int ic = r >> 5;                 // 32 float4-groups per ic
            const int p4 = (r & 31) * 4;
            float4 f = *reinterpret_cast<const float4*>(x + (size_t)ic * NPOS + pos0 + p4);
            s[ic][p4 + 0] = f.x; s[ic][p4 + 1] = f.y;
            s[ic][p4 + 2] = f.z; s[ic][p4 + 3] = f.w;
        }
        __syncthreads();
        // write: 1024 16B-chunks per block, 4 per thread, coalesced
#pragma unroll
        for (int i = 0; i < 4; i++) {
            const int c   = tid + i * 256;
            const int pos = c >> 3;
            const int ic0 = (c & 7) * 8;
            uint32_t pk[4];
#pragma unroll
            for (int j = 0; j < 4; j++) {
                __half h0 = __float2half(s[ic0 + 2*j][pos]);
                __half h1 = __float2half(s[ic0 + 2*j + 1][pos]);
                pk[j] = (uint32_t)__half_as_ushort(h0) | ((uint32_t)__half_as_ushort(h1) << 16);
            }
            *reinterpret_cast<uint4*>(g_x + (size_t)(pos0 + pos) * IN_C + ic0) =
                make_uint4(pk[0], pk[1], pk[2], pk[3]);
        }
    } else {
        const int idx = (blockIdx.x - 512) * 256 + tid;   // < 73728
        const int tap = idx >> 13;
        const int oc  = (idx >> 6) & 127;
        const int ic  = idx & 63;
        g_w[idx] = __float2half(w[((size_t)oc * IN_C + ic) * NTAPS + tap]);
    }
}

// ---------------- main HMMA conv kernel ----------------
// grid (2, 254): blockIdx.x = col tile (128 wide), blockIdx.y = output row
__global__ __launch_bounds__(256, 2)
void conv_hmma(const float* __restrict__ bias, float* __restrict__ out)
{
    extern __shared__ char smem[];
    const uint32_t sbase = smem_u32(smem);
    const int tid  = threadIdx.x;
    const int lane = tid & 31;
    const int wid  = tid >> 5;
    const int wm   = wid & 1;            // oc 0-63 / 64-127
    const int wn   = wid >> 1;           // 0..3, 32 positions each
    const int oh   = blockIdx.y;
    const int ow0  = blockIdx.x * N_TILE;

    // ldmatrix per-lane address components (validated mapping)
    const int rowA = ((lane >> 3) & 1) * 8 + (lane & 7);
    const int kbA  = (lane >> 4) * 16;
    const int rowB = ((lane >> 4) & 1) * 8 + (lane & 7);
    const int kbB  = ((lane >> 3) & 1) * 16;

    float acc[4][4][4];
#pragma unroll
    for (int a = 0; a < 4; a++)
#pragma unroll
        for (int b = 0; b < 4; b++)
#pragma unroll
            for (int c = 0; c < 4; c++) acc[a][b][c] = 0.0f;

    // ---- load the 3 B strips (once per CTA) ----
    auto issue_strips = [&]() {
        for (int i = tid; i < 3 * STRIP_CHUNKS; i += 256) {
            const int strip = i / STRIP_CHUNKS;
            const int c     = i - strip * STRIP_CHUNKS;
            const int y0    = (oh + strip) * IMG_W + ow0;
            cp_async16(sbase + SM_B + strip * STRIP_STRIDE + sw128((uint32_t)c * 16),
                       g_x + (size_t)y0 * IN_C + c * 8);
        }
    };
    // ---- load one weight tap tile into ring stage s ----
    auto issue_A = [&](int tap, int s) {
        const __half* src = g_w + (size_t)tap * OUT_C * IN_C;
        const uint32_t sb = sbase + SM_A + s * A_STAGE;
#pragma unroll
        for (int i = 0; i < 4; i++) {
            const uint32_t chunk = tid + i * 256;          // 0..1023
            cp_async16(sb + sw128(chunk * 16), src + chunk * 8);
        }
    };

    issue_strips();
    issue_A(0, 0);
    cp_commit();            // g0: strips + A0
    issue_A(1, 1);
    cp_commit();            // g1: A1

    int stage = 0;          // stage of tap t (t % 3)
#pragma unroll 1
    for (int t = 0; t < NTAPS; t++) {
        if (t < NTAPS - 1) cp_wait<1>(); else cp_wait<0>();
        __syncthreads();    // single barrier per tap (3-stage ring makes WAR safe)

        const int kh = t / 3;
        const int kw = t - kh * 3;
        const uint32_t aBase = sbase + SM_A + stage * A_STAGE;
        const uint32_t bBase = sbase + SM_B + kh * STRIP_STRIDE;

#pragma unroll
        for (int kc = 0; kc < 4; kc++) {
            uint32_t a[4][4];
#pragma unroll
            for (int mi = 0; mi < 4; mi++) {
                const uint32_t o = (uint32_t)(wm * 64 + mi * 16 + rowA) * 128 + kc * 32 + kbA;
                ldsm4(a[mi], aBase + sw128(o));
            }
#pragma unroll
            for (int nj = 0; nj < 2; nj++) {
                uint32_t b[4];
                const uint32_t brow = (uint32_t)(kw + wn * 32 + nj * 16 + rowB);
                const uint32_t o = brow * 128 + kc * 32 + kbB;
                ldsm4(b, bBase + sw128(o));
#pragma unroll
                for (int mi = 0; mi < 4; mi++) {
                    mma16816(acc[mi][nj * 2],     a[mi], b[0], b[1]);
                    mma16816(acc[mi][nj * 2 + 1], a[mi], b[2], b[3]);
                }
            }
        }

        if (t + 2 < NTAPS) {
            // stage (t+2)%3 was last read at tap t-1; the barrier above fenced it.
            int ws = stage + 2; if (ws >= 3) ws -= 3;
            issue_A(t + 2, ws);
            cp_commit();
        }
        if (++stage == 3) stage = 0;
    }

    // ---- epilogue: direct gmem stores ----
#pragma unroll
    for (int mi = 0; mi < 4; mi++) {
        const int oc0 = wm * 64 + mi * 16 + (lane >> 2);
        const float b0 = bias[oc0];
        const float b1 = bias[oc0 + 8];
#pragma unroll
        for (int ni = 0; ni < 4; ni++) {
            const int owp = ow0 + wn * 32 + ni * 8 + (lane & 3) * 2;
            if (owp < OUT_W) {
                float2 v0 = make_float2(acc[mi][ni][0] + b0, acc[mi][ni][1] + b0);
                float2 v1 = make_float2(acc[mi][ni][2] + b1, acc[mi][ni][3] + b1);
                *reinterpret_cast<float2*>(out + (size_t)oc0 * OUT_HW + oh * OUT_W + owp) = v0;
                *reinterpret_cast<float2*>(out + (size_t)(oc0 + 8) * OUT_HW + oh * OUT_W + owp) = v1;
            }
        }
    }
}

// ---------------- launch ----------------
extern "C" void kernel_launch(void* const* d_in, const int* in_sizes, int n_in,
                              void* d_out, int out_size)
{
    const float* x    = (const float*)d_in[0];
    const float* w    = (const float*)d_in[1];
    const float* bias = (const float*)d_in[2];
    float* out        = (float*)d_out;

    cudaFuncSetAttribute(conv_hmma, cudaFuncAttributeMaxDynamicSharedMemorySize, SMEM_TOTAL);

    prep<<<512 + (NTAPS * OUT_C * IN_C) / 256, 256>>>(x, w);
    conv_hmma<<<dim3(2, OUT_H), 256, SMEM_TOTAL>>>(bias, out);
}